// round 3
// baseline (speedup 1.0000x reference)
#include <cuda_runtime.h>
#include <stdint.h>

#define PI_F 3.14159265358979323846f
#define F0C  0.91f
#define NL   512      // EH*EW
#define EHc  16
#define EWc  32

// ---------------------------------------------------------------------------
// Kernel 1: fill entire output with grd_rgb * grd_acc (the "no scatter" case).
// Output is poisoned by the harness, so every element must be written.
// ---------------------------------------------------------------------------
__global__ void base_merge_kernel(const float* __restrict__ grd_rgb,
                                  const float* __restrict__ grd_acc,
                                  float* __restrict__ out, int n3)
{
    int j = blockIdx.x * blockDim.x + threadIdx.x;
    if (j < n3) {
        float a = grd_acc[j / 3];
        out[j] = grd_rgb[j] * a;
    }
}

// ---------------------------------------------------------------------------
// linear -> sRGB (matches reference exactly)
// ---------------------------------------------------------------------------
__device__ __forceinline__ float lin2srgb(float x)
{
    x = __saturatef(x);
    if (x <= 0.0031308f) return 12.92f * x;
    return 1.055f * powf(fmaxf(x, 1e-8f), 1.0f / 2.4f) - 0.055f;
}

// ---------------------------------------------------------------------------
// Kernel 2: one warp per surface point; lanes stride the 512 lights.
// ---------------------------------------------------------------------------
__global__ __launch_bounds__(256)
void render_kernel(const float* __restrict__ surf,
                   const float* __restrict__ ray_o,
                   const float* __restrict__ norm_raw,
                   const float* __restrict__ albedo,
                   const float* __restrict__ rough,
                   const float* __restrict__ lvis,
                   const float* __restrict__ xyz,
                   const float* __restrict__ area,
                   const float* __restrict__ probe,
                   const float* __restrict__ grd_rgb,
                   const float* __restrict__ grd_acc,
                   const int*   __restrict__ inds,
                   float* __restrict__ out,
                   int P)
{
    __shared__ float s_xyz [NL * 3];
    __shared__ float s_ldir[NL * 3];
    __shared__ float s_area[NL];
    __shared__ float s_probe[NL * 3];

    for (int i = threadIdx.x; i < NL * 3; i += blockDim.x) {
        s_xyz[i]   = xyz[i];
        s_probe[i] = probe[i];
    }
    for (int i = threadIdx.x; i < NL; i += blockDim.x) s_area[i] = area[i];
    __syncthreads();
    for (int i = threadIdx.x; i < NL; i += blockDim.x) {
        float x = s_xyz[i * 3 + 0], y = s_xyz[i * 3 + 1], z = s_xyz[i * 3 + 2];
        float inv = __fdividef(1.0f, sqrtf(x * x + y * y + z * z) + 1e-8f);
        s_ldir[i * 3 + 0] = x * inv;
        s_ldir[i * 3 + 1] = y * inv;
        s_ldir[i * 3 + 2] = z * inv;
    }
    __syncthreads();

    const int warp = threadIdx.x >> 5;
    const int lane = threadIdx.x & 31;
    const int p = blockIdx.x * (blockDim.x >> 5) + warp;
    if (p >= P) return;

    // ---- per-point invariants (all lanes compute redundantly; LDG broadcast) ----
    const float sx = surf[p * 3 + 0], sy = surf[p * 3 + 1], sz = surf[p * 3 + 2];

    float nx = norm_raw[p * 3 + 0], ny = norm_raw[p * 3 + 1], nz = norm_raw[p * 3 + 2];
    {
        float inv = __fdividef(1.0f, sqrtf(nx * nx + ny * ny + nz * nz) + 1e-8f);
        nx *= inv; ny *= inv; nz *= inv;
    }
    float cx = ray_o[p * 3 + 0] - sx, cy = ray_o[p * 3 + 1] - sy, cz = ray_o[p * 3 + 2] - sz;
    {
        float inv = __fdividef(1.0f, sqrtf(cx * cx + cy * cy + cz * cz) + 1e-8f);
        cx *= inv; cy *= inv; cz *= inv;
    }

    const float cos_v = nx * cx + ny * cy + nz * cz;
    const float acv   = fabsf(cos_v);
    const float r     = rough[p];
    const float a     = r * r;        // alpha
    const float a2    = a * a;        // alpha^2
    const float a2opi = a2 * (1.0f / PI_F);

    // tan_v^2 and the per-point part of the G term
    float cvs  = cos_v * cos_v;
    cvs        = fminf(cvs, 1.0f);
    float tanv = (cvs > 1e-12f) ? __fdividef(1.0f - cvs, cvs) : 0.0f;
    tanv       = fminf(tanv, 1e10f);
    const float g0 = __fdividef(2.0f, 1.0f + sqrtf(1.0f + a2 * tanv));

    const float aopR = albedo[p * 3 + 0] * (1.0f / PI_F);
    const float aopG = albedo[p * 3 + 1] * (1.0f / PI_F);
    const float aopB = albedo[p * 3 + 2] * (1.0f / PI_F);

    float accR = 0.0f, accG = 0.0f, accB = 0.0f;
    const float* __restrict__ lvp = lvis + (size_t)p * NL;

    #pragma unroll 4
    for (int li = lane; li < NL; li += 32) {
        const float lv = lvp[li];

        // surf -> light, normalized (norms ~10, rsqrt is safe vs eps path)
        float lx = s_xyz[li * 3 + 0] - sx;
        float ly = s_xyz[li * 3 + 1] - sy;
        float lz = s_xyz[li * 3 + 2] - sz;
        const float invl = rsqrtf(lx * lx + ly * ly + lz * lz);
        lx *= invl; ly *= invl; lz *= invl;

        // --- envmap bilinear sample at direction (lx,ly,lz) ---
        const float zz = fminf(fmaxf(lz, -1.0f + 1e-6f), 1.0f - 1e-6f);
        const float v  = acosf(zz) * ((float)EHc / PI_F) - 0.5f;
        const float u  = atan2f(ly, lx) * ((float)EWc / (2.0f * PI_F)) + (0.5f * EWc - 0.5f);
        const float v0f = floorf(v), u0f = floorf(u);
        const float fv = v - v0f, fu = u - u0f;
        int v0 = (int)v0f; v0 = v0 < 0 ? 0 : v0;
        int v1 = v0 + 1; v1 = v1 > (EHc - 1) ? (EHc - 1) : v1;
        const int u0 = ((int)u0f + EWc) & (EWc - 1);
        const int u1 = (u0 + 1) & (EWc - 1);
        const float* P00 = s_probe + (v0 * EWc + u0) * 3;
        const float* P01 = s_probe + (v0 * EWc + u1) * 3;
        const float* P10 = s_probe + (v1 * EWc + u0) * 3;
        const float* P11 = s_probe + (v1 * EWc + u1) * 3;
        const float w00 = (1.0f - fu) * (1.0f - fv);
        const float w01 = fu * (1.0f - fv);
        const float w10 = (1.0f - fu) * fv;
        const float w11 = fu * fv;
        const float LR = P00[0] * w00 + P01[0] * w01 + P10[0] * w10 + P11[0] * w11;
        const float LG = P00[1] * w00 + P01[1] * w01 + P10[1] * w10 + P11[1] * w11;
        const float LB = P00[2] * w00 + P01[2] * w01 + P10[2] * w10 + P11[2] * w11;

        // ldot uses normalized xyz (not surf2light)
        const float ldot = s_ldir[li * 3 + 0] * nx + s_ldir[li * 3 + 1] * ny + s_ldir[li * 3 + 2] * nz;

        // --- microfacet BRDF ---
        float hx = lx + cx, hy = ly + cy, hz = lz + cz;
        const float invh = __fdividef(1.0f, sqrtf(hx * hx + hy * hy + hz * hz) + 1e-8f);
        hx *= invh; hy *= invh; hz *= invh;

        const float ldh = lx * hx + ly * hy + lz * hz;
        const float t   = 1.0f - ldh;
        const float t2  = t * t;
        const float f   = F0C + (1.0f - F0C) * (t2 * t2 * t);

        const float cm  = hx * nx + hy * ny + hz * nz;
        const float cms = cm * cm;
        // pi*cos^4*(a2+tan^2)^2 == pi*(cms*(a2-1)+1)^2
        const float w   = fmaf(cms, a2 - 1.0f, 1.0f);
        const float d   = (cm > 0.0f && cms > 1e-12f) ? __fdividef(a2opi, w * w) : 0.0f;

        const float chv = hx * cx + hy * cy + hz * cz;
        const float g   = (chv * cos_v > 0.0f) ? g0 : 0.0f;

        const float ldn = lx * nx + ly * ny + lz * nz;
        const float den = 4.0f * fabsf(ldn) * acv;
        const float micro = (den > 1e-12f) ? __fdividef(f * g * d, den) : 0.0f;

        const float s = lv * ldot * s_area[li];
        accR = fmaf(micro + aopR, s * LR, accR);
        accG = fmaf(micro + aopG, s * LG, accG);
        accB = fmaf(micro + aopB, s * LB, accB);
    }

    // warp reduce
    #pragma unroll
    for (int off = 16; off; off >>= 1) {
        accR += __shfl_xor_sync(0xffffffffu, accR, off);
        accG += __shfl_xor_sync(0xffffffffu, accG, off);
        accB += __shfl_xor_sync(0xffffffffu, accB, off);
    }

    if (lane == 0) {
        const int ind = inds[p];
        // inds is sorted; JAX scatter-set applies updates in order -> last dup wins
        const bool last = (p == P - 1) || (inds[p + 1] != ind);
        if (last) {
            const float ac   = grd_acc[ind];
            const float omac = 1.0f - ac;
            out[ind * 3 + 0] = grd_rgb[ind * 3 + 0] * ac + lin2srgb(accR) * omac;
            out[ind * 3 + 1] = grd_rgb[ind * 3 + 1] * ac + lin2srgb(accG) * omac;
            out[ind * 3 + 2] = grd_rgb[ind * 3 + 2] * ac + lin2srgb(accB) * omac;
        }
    }
}

// ---------------------------------------------------------------------------
extern "C" void kernel_launch(void* const* d_in, const int* in_sizes, int n_in,
                              void* d_out, int out_size)
{
    const float* surf     = (const float*)d_in[0];
    const float* ray_o    = (const float*)d_in[1];
    const float* norm_raw = (const float*)d_in[2];
    const float* albedo   = (const float*)d_in[3];
    const float* rough    = (const float*)d_in[4];
    const float* lvis     = (const float*)d_in[5];
    const float* xyz      = (const float*)d_in[6];
    const float* area     = (const float*)d_in[7];
    const float* probe    = (const float*)d_in[8];
    const float* grd_rgb  = (const float*)d_in[9];
    const float* grd_acc  = (const float*)d_in[10];
    const int*   inds     = (const int*)  d_in[11];
    float* out = (float*)d_out;

    const int P  = in_sizes[11];   // 8192 points
    const int n3 = out_size;       // 65536*3

    base_merge_kernel<<<(n3 + 255) / 256, 256>>>(grd_rgb, grd_acc, out, n3);

    const int warpsPerBlock = 8;
    const int blocks = (P + warpsPerBlock - 1) / warpsPerBlock;
    render_kernel<<<blocks, 256>>>(surf, ray_o, norm_raw, albedo, rough, lvis,
                                   xyz, area, probe, grd_rgb, grd_acc, inds,
                                   out, P);
}